// round 10
// baseline (speedup 1.0000x reference)
#include <cuda_runtime.h>
#include <cuda_bf16.h>
#include <math.h>

// SetConv1dDecoder: out[b,m,c] = sum_n exp(-0.5*(x[b,m]-xz[n])^2 / scale^2) * z[b,c,n]
// Weight in grid steps = exp(-k^2/8); 20-pt window, 4-aligned -> rel_err ~4e-5.
//
// R10: SINGLE kernel (no transpose, no 2nd launch). 1 target/warp, lane=(c,seg):
// each lane reads its channel's window span contiguously (3 batched LDG.128).
// Gaussian weights via multiplicative recurrence (3 exps/warp total):
//   w_{k+1} = w_k * r_k,  r_{k+1} = r_k * rho,  rho = exp(-2*alpha*s^2).
// seg1's 3rd float4 is a dup pad -> weight forced to 0 (edge-safe).

__global__ void __launch_bounds__(256) setconv_direct_c16(
        const float* __restrict__ xz,
        const float* __restrict__ x,
        const float* __restrict__ z,
        const float* __restrict__ log_scale,
        float* __restrict__ out,
        int BM, int M, int mshift, int N, int out_off)
{
    const int gid  = blockIdx.x * blockDim.x + threadIdx.x;

    // tuple head: copy xz (first out_off threads)
    if (gid < out_off) out[gid] = xz[gid];

    const int t    = gid >> 5;            // one warp per target
    const int lane = threadIdx.x & 31;
    if (t >= BM) return;

    const int c   = lane & 15;            // channel
    const int seg = lane >> 4;            // 0: pts 0..11, 1: pts 12..19 (+pad)

    const float ls    = __ldg(log_scale);
    const float xz0   = __ldg(xz);
    const float xz1   = __ldg(xz + 1);
    const float xv    = __ldg(x + t);     // same addr per warp -> broadcast

    const float step  = xz1 - xz0;
    const float alpha = 0.5f * __expf(-2.0f * ls);      // 1/(2*scale^2)
    const float inv_step = __fdividef(1.0f, step);

    const int b = (mshift >= 0) ? (t >> mshift) : (t / M);

    int i0 = (((int)floorf((xv - xz0) * inv_step)) - 8) & ~3;
    i0 = min(max(i0, 0), N - 20);

    // lane's contiguous span start: seg0 -> i0, seg1 -> i0+12 (both 16B-aligned)
    const float* base = z + (size_t)b * 16 * N + (size_t)c * N + i0 + seg * 12;

    // 3 batched LDG.128: seg0 reads floats 0..11; seg1 reads 0..7 + dup of 4..7
    const float4* p0 = (const float4*)base;
    const float4* p1 = p0 + 1;
    const float4* p2 = p0 + (seg ? 1 : 2);   // seg1: dup (weight zeroed below)

    float4 v0, v1, v2;
    asm volatile(
        "ld.global.nc.v4.f32 {%0,%1,%2,%3},   [%12];\n\t"
        "ld.global.nc.v4.f32 {%4,%5,%6,%7},   [%13];\n\t"
        "ld.global.nc.v4.f32 {%8,%9,%10,%11}, [%14];\n\t"
        : "=f"(v0.x), "=f"(v0.y), "=f"(v0.z), "=f"(v0.w),
          "=f"(v1.x), "=f"(v1.y), "=f"(v1.z), "=f"(v1.w),
          "=f"(v2.x), "=f"(v2.y), "=f"(v2.z), "=f"(v2.w)
        : "l"(p0), "l"(p1), "l"(p2));

    // Gaussian recurrence along the lane's 12 points.
    const float p_first = (float)(i0 + seg * 12);
    float d = xv - (xz0 + p_first * step);          // distance at first point
    const float as  = alpha * step;
    float w   = __expf(-alpha * d * d);             // w_0
    float r   = __expf(as * (2.0f * d - step));     // w_1/w_0
    const float rho = __expf(-2.0f * as * step);    // r_{k+1}/r_k (const < 1)

    float acc = 0.0f;
#define PT(E) { acc += w * (E); w *= r; r *= rho; }
    PT(v0.x) PT(v0.y) PT(v0.z) PT(v0.w)
    PT(v1.x) PT(v1.y) PT(v1.z) PT(v1.w)
    if (seg) w = 0.0f;                  // pad float4 contributes nothing
    PT(v2.x) PT(v2.y) PT(v2.z) PT(v2.w)
#undef PT

    // fold the two segs (lane l <- l+16)
    acc += __shfl_xor_sync(0xffffffffu, acc, 16);

    if (seg == 0)
        out[out_off + (size_t)t * 16 + c] = acc;    // 64B coalesced per warp
}

// Generic fallback (full accuracy, 32-pt window).
__global__ void setconv_generic_kernel(const float* __restrict__ xz,
                                       const float* __restrict__ x,
                                       const float* __restrict__ z,
                                       const float* __restrict__ log_scale,
                                       float* __restrict__ out,
                                       int BM, int M, int C, int N, int out_off)
{
    const int tid = blockIdx.x * blockDim.x + threadIdx.x;
    if (tid < out_off) out[tid] = xz[tid];
    if (tid >= BM) return;

    const int b = tid / M;
    const float ls       = *log_scale;
    const float alpha    = 0.5f * __expf(-2.0f * ls);
    const float xz0      = xz[0];
    const float step     = xz[1] - xz[0];
    const float inv_step = 1.0f / step;
    const float xv = x[tid];

    int i0 = (int)floorf((xv - xz0) * inv_step) - 15;
    i0 = min(max(i0, 0), N - 32);

    const float* zb = z + (size_t)b * C * N;

    float w[32];
#pragma unroll
    for (int k = 0; k < 32; ++k) {
        float d = xv - (xz0 + (float)(i0 + k) * step);
        w[k] = __expf(-alpha * d * d);
    }

    for (int cc = 0; cc < C; ++cc) {
        const float* zp = zb + (size_t)cc * N + i0;
        float s = 0.0f;
#pragma unroll
        for (int k = 0; k < 32; ++k) s += w[k] * zp[k];
        out[out_off + (size_t)tid * C + cc] = s;
    }
}

extern "C" void kernel_launch(void* const* d_in, const int* in_sizes, int n_in,
                              void* d_out, int out_size)
{
    const float* xz = (const float*)d_in[0];   // [N,1]
    const float* x  = (const float*)d_in[1];   // [B,M,1]
    const float* z  = (const float*)d_in[2];   // [B,C,N]
    const float* ls = (const float*)d_in[3];   // scalar

    const int N   = in_sizes[0];
    const int BM  = in_sizes[1];
    const int BCN = in_sizes[2];
    const int BC  = BCN / N;

    int C, out_off;
    if ((out_size - N) > 0 && (out_size - N) % BM == 0 &&
        (BC % ((out_size - N) / BM)) == 0) {
        C = (out_size - N) / BM;   // tuple output: [xz | out]
        out_off = N;
    } else {
        C = out_size / BM;
        out_off = 0;
    }
    const int B = BC / C;
    const int M = BM / B;

    float* out = (float*)d_out;

    if (C == 16 && N >= 32) {
        int mshift = -1;
        if ((M & (M - 1)) == 0) { mshift = 0; while ((1 << mshift) < M) ++mshift; }

        const long long lanes = (long long)BM * 32;
        const long long work  = (lanes > out_off) ? lanes : out_off;
        const int threads = 256;
        const int blocks  = (int)((work + threads - 1) / threads);
        setconv_direct_c16<<<blocks, threads>>>(xz, x, z, ls, out,
                                                BM, M, mshift, N, out_off);
    } else {
        const int threads = 128;
        const int work    = (BM > out_off) ? BM : out_off;
        const int blocks  = (work + threads - 1) / threads;
        setconv_generic_kernel<<<blocks, threads>>>(xz, x, z, ls, out, BM, M, C, N, out_off);
    }
}

// round 11
// speedup vs baseline: 1.1254x; 1.1254x over previous
#include <cuda_runtime.h>
#include <cuda_bf16.h>
#include <math.h>

// SetConv1dDecoder: out[b,m,c] = sum_n exp(-0.5*(x[b,m]-xz[n])^2 / scale^2) * z[b,c,n]
// Weight in grid steps = exp(-k^2/8); 20-pt window -> rel_err ~4e-5 (40x under gate).
//
// R11: FUSED persistent kernel. Phase A: smem-tile transpose z[B,C,N]->zt[B,N,C]
// (grid-strided) + xz tuple-head copy. Software sense-reversing grid barrier
// (4 CTAs/SM -> co-resident, no deadlock; self-resetting across graph replays).
// Phase B: R9 compute body (2 targets/warp, 16 lanes/target, 5 asm-batched
// LDG.128 -> MLP=5, 2 shfl_xor folds, 64B stores), grid-strided over target pairs.

#define WIN 20

__device__ float g_zt[1 << 22];                 // transpose scratch
__device__ unsigned g_bar_count = 0;            // barrier arrivals
__device__ volatile unsigned g_bar_sense = 0;   // barrier phase (flips per use)

__global__ void __launch_bounds__(256) setconv_fused_c16(
        const float* __restrict__ xz,
        const float* __restrict__ x,
        const float* __restrict__ z,
        float* __restrict__ zt,
        const float* __restrict__ log_scale,
        float* __restrict__ out,
        int B, int BM, int M, int mshift, int N, int ntile, int out_off)
{
    __shared__ float s[16][65];
    const int tid  = threadIdx.x;
    const int lane = tid & 31;
    const int wid  = tid >> 5;

    // ---------------- Phase A: xz copy + transpose ----------------
    for (int i = blockIdx.x * 256 + tid; i < out_off; i += gridDim.x * 256)
        out[i] = xz[i];

    for (int tile = blockIdx.x; tile < B * ntile; tile += gridDim.x) {
        const int b  = tile / ntile;
        const int n0 = (tile % ntile) * 64;
        const float* zb = z + (size_t)b * 16 * N;

        {   // gather: thread (c = tid>>4, q = tid&15) loads float4 at n = 4q
            const int c = tid >> 4;
            const int n = 4 * (tid & 15);
            if (n0 + n + 3 < N) {
                float4 v = __ldg((const float4*)(zb + (size_t)c * N + n0 + n));
                s[c][n + 0] = v.x; s[c][n + 1] = v.y;
                s[c][n + 2] = v.z; s[c][n + 3] = v.w;
            } else {
                for (int j = 0; j < 4; ++j)
                    if (n0 + n + j < N) s[c][n + j] = zb[(size_t)c * N + n0 + n + j];
            }
        }
        __syncthreads();
        {   // scatter: thread (n = tid>>2, g = tid&3) writes channels 4g..4g+3
            const int n = tid >> 2;
            const int g = tid & 3;
            if (n0 + n < N) {
                float4 v = make_float4(s[4*g+0][n], s[4*g+1][n],
                                       s[4*g+2][n], s[4*g+3][n]);
                *(float4*)(zt + ((size_t)b * N + n0 + n) * 16 + 4 * g) = v;
            }
        }
        __syncthreads();
    }

    // ---------------- grid barrier (sense-reversing, self-resetting) ----------
    __threadfence();              // my zt writes -> GPU-visible
    __syncthreads();
    if (tid == 0) {
        const unsigned my = g_bar_sense;
        const unsigned n  = atomicAdd(&g_bar_count, 1u);
        if (n == gridDim.x - 1) {
            g_bar_count = 0;      // reset for next replay
            __threadfence();
            g_bar_sense = my ^ 1u;
        } else {
            while (g_bar_sense == my) __nanosleep(64);
        }
    }
    __syncthreads();

    // ---------------- Phase B: compute (2 targets per warp) ----------------
    const float ls       = __ldg(log_scale);
    const float xz0      = __ldg(xz);
    const float step     = __ldg(xz + 1) - xz0;
    const float alpha    = 0.5f * __expf(-2.0f * ls);   // 1/(2*scale^2)
    const float inv_step = __fdividef(1.0f, step);
    const float dstep    = 4.0f * step;

    const int tgt = lane >> 4;        // target within warp (0/1)
    const int sub = lane & 15;        // r-slot*4 + ch-group
    const int r   = sub >> 2;         // row slot: rows r, r+4, ..., r+16
    const int cg  = sub & 3;          // channel group (float4)

    const int npairs = (BM + 1) / 2;
    const int wstride = gridDim.x * 8;

    for (int w = blockIdx.x * 8 + wid; w < npairs; w += wstride) {
        const int  t0    = w * 2;
        const bool valid = (t0 + tgt) < BM;
        const int  t     = valid ? (t0 + tgt) : (BM - 1);

        const float xv = __ldg(x + t);
        const int   b  = (mshift >= 0) ? (t >> mshift) : (t / M);

        int i0 = (((int)floorf((xv - xz0) * inv_step)) - 8) & ~3;
        i0 = min(max(i0, 0), N - WIN);

        // lane's stream: float4 index sub + 16k, k = 0..4
        const float4* p = (const float4*)(zt + ((size_t)b * N + i0) * 16) + sub;

        float4 v0, v1, v2, v3, v4;
        asm volatile(
            "ld.global.nc.v4.f32 {%0,%1,%2,%3},     [%20];\n\t"
            "ld.global.nc.v4.f32 {%4,%5,%6,%7},     [%21];\n\t"
            "ld.global.nc.v4.f32 {%8,%9,%10,%11},   [%22];\n\t"
            "ld.global.nc.v4.f32 {%12,%13,%14,%15}, [%23];\n\t"
            "ld.global.nc.v4.f32 {%16,%17,%18,%19}, [%24];\n\t"
            : "=f"(v0.x), "=f"(v0.y), "=f"(v0.z), "=f"(v0.w),
              "=f"(v1.x), "=f"(v1.y), "=f"(v1.z), "=f"(v1.w),
              "=f"(v2.x), "=f"(v2.y), "=f"(v2.z), "=f"(v2.w),
              "=f"(v3.x), "=f"(v3.y), "=f"(v3.z), "=f"(v3.w),
              "=f"(v4.x), "=f"(v4.y), "=f"(v4.z), "=f"(v4.w)
            : "l"(p), "l"(p + 16), "l"(p + 32), "l"(p + 48), "l"(p + 64));

        const float d0 = xv - (xz0 + (float)(i0 + r) * step);

        float4 acc = make_float4(0.f, 0.f, 0.f, 0.f);
#define STEP(K, V)                                                  \
        {   float d = d0 - (float)(K) * dstep;                      \
            float wgt = __expf(-alpha * d * d);                     \
            acc.x += wgt * (V).x; acc.y += wgt * (V).y;             \
            acc.z += wgt * (V).z; acc.w += wgt * (V).w; }
        STEP(0, v0) STEP(1, v1) STEP(2, v2) STEP(3, v3) STEP(4, v4)
#undef STEP

        // fold the 4 r-slots (lane bits 2,3)
#pragma unroll
        for (int off = 4; off <= 8; off <<= 1) {
            acc.x += __shfl_xor_sync(0xffffffffu, acc.x, off);
            acc.y += __shfl_xor_sync(0xffffffffu, acc.y, off);
            acc.z += __shfl_xor_sync(0xffffffffu, acc.z, off);
            acc.w += __shfl_xor_sync(0xffffffffu, acc.w, off);
        }

        if (sub < 4 && valid) {
            float4* op = (float4*)(out + out_off + (size_t)t * 16);
            op[cg] = acc;              // 64B per target, 128B per warp
        }
    }
}

// Generic fallback (full accuracy, 32-pt window).
__global__ void setconv_generic_kernel(const float* __restrict__ xz,
                                       const float* __restrict__ x,
                                       const float* __restrict__ z,
                                       const float* __restrict__ log_scale,
                                       float* __restrict__ out,
                                       int BM, int M, int C, int N, int out_off)
{
    const int tid = blockIdx.x * blockDim.x + threadIdx.x;
    if (tid < out_off) out[tid] = xz[tid];
    if (tid >= BM) return;

    const int b = tid / M;
    const float ls       = *log_scale;
    const float alpha    = 0.5f * __expf(-2.0f * ls);
    const float xz0      = xz[0];
    const float step     = xz[1] - xz[0];
    const float inv_step = 1.0f / step;
    const float xv = x[tid];

    int i0 = (int)floorf((xv - xz0) * inv_step) - 15;
    i0 = min(max(i0, 0), N - 32);

    const float* zb = z + (size_t)b * C * N;

    float w[32];
#pragma unroll
    for (int k = 0; k < 32; ++k) {
        float d = xv - (xz0 + (float)(i0 + k) * step);
        w[k] = __expf(-alpha * d * d);
    }

    for (int cc = 0; cc < C; ++cc) {
        const float* zp = zb + (size_t)cc * N + i0;
        float s = 0.0f;
#pragma unroll
        for (int k = 0; k < 32; ++k) s += w[k] * zp[k];
        out[out_off + (size_t)tid * C + cc] = s;
    }
}

extern "C" void kernel_launch(void* const* d_in, const int* in_sizes, int n_in,
                              void* d_out, int out_size)
{
    const float* xz = (const float*)d_in[0];   // [N,1]
    const float* x  = (const float*)d_in[1];   // [B,M,1]
    const float* z  = (const float*)d_in[2];   // [B,C,N]
    const float* ls = (const float*)d_in[3];   // scalar

    const int N   = in_sizes[0];
    const int BM  = in_sizes[1];
    const int BCN = in_sizes[2];
    const int BC  = BCN / N;

    int C, out_off;
    if ((out_size - N) > 0 && (out_size - N) % BM == 0 &&
        (BC % ((out_size - N) / BM)) == 0) {
        C = (out_size - N) / BM;   // tuple output: [xz | out]
        out_off = N;
    } else {
        C = out_size / BM;
        out_off = 0;
    }
    const int B = BC / C;
    const int M = BM / B;

    float* out = (float*)d_out;

    if (C == 16 && N >= 32 && (size_t)BCN <= (size_t)(1 << 22)) {
        float* zt;
        cudaGetSymbolAddress((void**)&zt, g_zt);

        int dev = 0, nsm = 148;
        cudaGetDevice(&dev);
        cudaDeviceGetAttribute(&nsm, cudaDevAttrMultiProcessorCount, dev);

        int mshift = -1;
        if ((M & (M - 1)) == 0) { mshift = 0; while ((1 << mshift) < M) ++mshift; }

        const int ntile = (N + 63) / 64;
        const int grid  = nsm * 4;   // 4 CTAs/SM: co-resident -> barrier is safe

        setconv_fused_c16<<<grid, 256>>>(xz, x, z, zt, ls, out,
                                         B, BM, M, mshift, N, ntile, out_off);
    } else {
        const int threads = 128;
        const int work    = (BM > out_off) ? BM : out_off;
        const int blocks  = (work + threads - 1) / threads;
        setconv_generic_kernel<<<blocks, threads>>>(xz, x, z, ls, out, BM, M, C, N, out_off);
    }
}

// round 12
// speedup vs baseline: 1.1522x; 1.0239x over previous
#include <cuda_runtime.h>
#include <cuda_bf16.h>
#include <math.h>

// SetConv1dDecoder: out[b,m,c] = sum_n exp(-0.5*(x[b,m]-xz[n])^2 / scale^2) * z[b,c,n]
// Weight in grid steps = exp(-k^2/8); 20-pt window -> rel_err ~4e-5 (25x under gate).
//
// R12: fused persistent kernel, barrier fixed.
//  - pure-spin sense-reversing grid barrier (NO __nanosleep -- its wake quantum
//    was the suspected 4-5us overhead in R11)
//  - __launch_bounds__(256,4) + grid=4*SM: all CTAs wave-1 resident by
//    construction -> spin barrier cannot deadlock
//  - phase A: smem transpose z[B,C,N]->zt[B,N,C] (one 64-col tile per CTA)
//  - phase B: R9 body (2 targets/warp, 16 lanes/target, 5 asm-batched LDG.128)

#define WIN 20

__device__ float g_zt[1 << 22];                 // transpose scratch
__device__ unsigned g_bar_count = 0;
__device__ volatile unsigned g_bar_sense = 0;

__global__ void __launch_bounds__(256, 4) setconv_fused_c16(
        const float* __restrict__ xz,
        const float* __restrict__ x,
        const float* __restrict__ z,
        float* __restrict__ zt,
        const float* __restrict__ log_scale,
        float* __restrict__ out,
        int B, int BM, int M, int mshift, int N, int ntile, int out_off)
{
    __shared__ float s[16][65];
    const int tid  = threadIdx.x;
    const int lane = tid & 31;
    const int wid  = tid >> 5;

    // ---------------- Phase A: xz copy + transpose (grid-strided tiles) -------
    for (int i = blockIdx.x * 256 + tid; i < out_off; i += gridDim.x * 256)
        out[i] = xz[i];

    for (int tile = blockIdx.x; tile < B * ntile; tile += gridDim.x) {
        const int b  = tile / ntile;
        const int n0 = (tile % ntile) * 64;
        const float* zb = z + (size_t)b * 16 * N;

        {   // gather: thread (c = tid>>4, q = tid&15) loads float4 at n = 4q
            const int c = tid >> 4;
            const int n = 4 * (tid & 15);
            if (n0 + n + 3 < N) {
                float4 v = __ldg((const float4*)(zb + (size_t)c * N + n0 + n));
                s[c][n + 0] = v.x; s[c][n + 1] = v.y;
                s[c][n + 2] = v.z; s[c][n + 3] = v.w;
            } else {
                for (int j = 0; j < 4; ++j)
                    if (n0 + n + j < N) s[c][n + j] = zb[(size_t)c * N + n0 + n + j];
            }
        }
        __syncthreads();
        {   // scatter: thread (n = tid>>2, g = tid&3) writes channels 4g..4g+3
            const int n = tid >> 2;
            const int g = tid & 3;
            if (n0 + n < N) {
                float4 v = make_float4(s[4*g+0][n], s[4*g+1][n],
                                       s[4*g+2][n], s[4*g+3][n]);
                *(float4*)(zt + ((size_t)b * N + n0 + n) * 16 + 4 * g) = v;
            }
        }
        __syncthreads();
    }

    // ---------------- grid barrier: sense-reversing, PURE SPIN ----------------
    __threadfence();                      // publish zt
    __syncthreads();
    if (tid == 0) {
        const unsigned my = g_bar_sense;
        if (atomicAdd(&g_bar_count, 1u) == gridDim.x - 1) {
            g_bar_count = 0;              // reset for next graph replay
            __threadfence();
            g_bar_sense = my ^ 1u;
        } else {
            while (g_bar_sense == my) { } // L2 poll, ~250cyc wake
        }
    }
    __syncthreads();

    // ---------------- Phase B: compute (2 targets per warp) -------------------
    const float ls       = __ldg(log_scale);
    const float xz0      = __ldg(xz);
    const float step     = __ldg(xz + 1) - xz0;
    const float alpha    = 0.5f * __expf(-2.0f * ls);   // 1/(2*scale^2)
    const float inv_step = __fdividef(1.0f, step);
    const float dstep    = 4.0f * step;

    const int tgt = lane >> 4;        // target within warp (0/1)
    const int sub = lane & 15;        // r-slot*4 + ch-group
    const int r   = sub >> 2;         // row slot: rows r, r+4, ..., r+16
    const int cg  = sub & 3;          // channel group (float4)

    const int npairs  = (BM + 1) / 2;
    const int wstride = gridDim.x * 8;

    for (int w = blockIdx.x * 8 + wid; w < npairs; w += wstride) {
        const int  t0    = w * 2;
        const bool valid = (t0 + tgt) < BM;
        const int  t     = valid ? (t0 + tgt) : (BM - 1);

        const float xv = __ldg(x + t);
        const int   b  = (mshift >= 0) ? (t >> mshift) : (t / M);

        int i0 = (((int)floorf((xv - xz0) * inv_step)) - 8) & ~3;
        i0 = min(max(i0, 0), N - WIN);

        const float4* p = (const float4*)(zt + ((size_t)b * N + i0) * 16) + sub;

        float4 v0, v1, v2, v3, v4;
        asm volatile(
            "ld.global.nc.v4.f32 {%0,%1,%2,%3},     [%20];\n\t"
            "ld.global.nc.v4.f32 {%4,%5,%6,%7},     [%21];\n\t"
            "ld.global.nc.v4.f32 {%8,%9,%10,%11},   [%22];\n\t"
            "ld.global.nc.v4.f32 {%12,%13,%14,%15}, [%23];\n\t"
            "ld.global.nc.v4.f32 {%16,%17,%18,%19}, [%24];\n\t"
            : "=f"(v0.x), "=f"(v0.y), "=f"(v0.z), "=f"(v0.w),
              "=f"(v1.x), "=f"(v1.y), "=f"(v1.z), "=f"(v1.w),
              "=f"(v2.x), "=f"(v2.y), "=f"(v2.z), "=f"(v2.w),
              "=f"(v3.x), "=f"(v3.y), "=f"(v3.z), "=f"(v3.w),
              "=f"(v4.x), "=f"(v4.y), "=f"(v4.z), "=f"(v4.w)
            : "l"(p), "l"(p + 16), "l"(p + 32), "l"(p + 48), "l"(p + 64));

        const float d0 = xv - (xz0 + (float)(i0 + r) * step);

        float4 acc = make_float4(0.f, 0.f, 0.f, 0.f);
#define STEP(K, V)                                                  \
        {   float d = d0 - (float)(K) * dstep;                      \
            float wgt = __expf(-alpha * d * d);                     \
            acc.x += wgt * (V).x; acc.y += wgt * (V).y;             \
            acc.z += wgt * (V).z; acc.w += wgt * (V).w; }
        STEP(0, v0) STEP(1, v1) STEP(2, v2) STEP(3, v3) STEP(4, v4)
#undef STEP

#pragma unroll
        for (int off = 4; off <= 8; off <<= 1) {
            acc.x += __shfl_xor_sync(0xffffffffu, acc.x, off);
            acc.y += __shfl_xor_sync(0xffffffffu, acc.y, off);
            acc.z += __shfl_xor_sync(0xffffffffu, acc.z, off);
            acc.w += __shfl_xor_sync(0xffffffffu, acc.w, off);
        }

        if (sub < 4 && valid) {
            float4* op = (float4*)(out + out_off + (size_t)t * 16);
            op[cg] = acc;
        }
    }
}

// Generic fallback (full accuracy, 32-pt window).
__global__ void setconv_generic_kernel(const float* __restrict__ xz,
                                       const float* __restrict__ x,
                                       const float* __restrict__ z,
                                       const float* __restrict__ log_scale,
                                       float* __restrict__ out,
                                       int BM, int M, int C, int N, int out_off)
{
    const int tid = blockIdx.x * blockDim.x + threadIdx.x;
    if (tid < out_off) out[tid] = xz[tid];
    if (tid >= BM) return;

    const int b = tid / M;
    const float ls       = *log_scale;
    const float alpha    = 0.5f * __expf(-2.0f * ls);
    const float xz0      = xz[0];
    const float step     = xz[1] - xz[0];
    const float inv_step = 1.0f / step;
    const float xv = x[tid];

    int i0 = (int)floorf((xv - xz0) * inv_step) - 15;
    i0 = min(max(i0, 0), N - 32);

    const float* zb = z + (size_t)b * C * N;

    float w[32];
#pragma unroll
    for (int k = 0; k < 32; ++k) {
        float d = xv - (xz0 + (float)(i0 + k) * step);
        w[k] = __expf(-alpha * d * d);
    }

    for (int cc = 0; cc < C; ++cc) {
        const float* zp = zb + (size_t)cc * N + i0;
        float sacc = 0.0f;
#pragma unroll
        for (int k = 0; k < 32; ++k) sacc += w[k] * zp[k];
        out[out_off + (size_t)tid * C + cc] = sacc;
    }
}

extern "C" void kernel_launch(void* const* d_in, const int* in_sizes, int n_in,
                              void* d_out, int out_size)
{
    const float* xz = (const float*)d_in[0];   // [N,1]
    const float* x  = (const float*)d_in[1];   // [B,M,1]
    const float* z  = (const float*)d_in[2];   // [B,C,N]
    const float* ls = (const float*)d_in[3];   // scalar

    const int N   = in_sizes[0];
    const int BM  = in_sizes[1];
    const int BCN = in_sizes[2];
    const int BC  = BCN / N;

    int C, out_off;
    if ((out_size - N) > 0 && (out_size - N) % BM == 0 &&
        (BC % ((out_size - N) / BM)) == 0) {
        C = (out_size - N) / BM;   // tuple output: [xz | out]
        out_off = N;
    } else {
        C = out_size / BM;
        out_off = 0;
    }
    const int B = BC / C;
    const int M = BM / B;

    float* out = (float*)d_out;

    if (C == 16 && N >= 32 && (size_t)BCN <= (size_t)(1 << 22)) {
        float* zt;
        cudaGetSymbolAddress((void**)&zt, g_zt);

        int dev = 0, nsm = 148;
        cudaGetDevice(&dev);
        cudaDeviceGetAttribute(&nsm, cudaDevAttrMultiProcessorCount, dev);

        int mshift = -1;
        if ((M & (M - 1)) == 0) { mshift = 0; while ((1 << mshift) < M) ++mshift; }

        const int ntile = (N + 63) / 64;
        const int grid  = nsm * 4;   // matches __launch_bounds__(256,4): wave-1 resident

        setconv_fused_c16<<<grid, 256>>>(xz, x, z, zt, ls, out,
                                         B, BM, M, mshift, N, ntile, out_off);
    } else {
        const int threads = 128;
        const int work    = (BM > out_off) ? BM : out_off;
        const int blocks  = (work + threads - 1) / threads;
        setconv_generic_kernel<<<blocks, threads>>>(xz, x, z, ls, out, BM, M, C, N, out_off);
    }
}

// round 13
// speedup vs baseline: 1.4244x; 1.2362x over previous
#include <cuda_runtime.h>
#include <cuda_bf16.h>
#include <math.h>

// SetConv1dDecoder: out[b,m,c] = sum_n exp(-0.5*(x[b,m]-xz[n])^2 / scale^2) * z[b,c,n]
// Weight in grid steps = exp(-k^2/8); 20-pt window -> rel_err ~4e-5 (25x under gate).
//
// R13: two-kernel R9 structure + PDL. Transpose triggers programmatic launch
// completion after its stores; compute kernel runs its prologue (x load, window
// math) overlapped with the transpose tail and grid-dependency-syncs only
// before reading zt. 32-bit zt offsets. Host falls back to plain launches if
// the PDL launch is rejected.

#define WIN 20

__device__ float g_zt[1 << 22];   // transpose scratch

// ---- Phase 1: transpose z[B,C,N] -> zt[B,N,C] (C==16) + xz tuple-head copy.
__global__ void __launch_bounds__(256) transpose_z16(
        const float* __restrict__ z, float* __restrict__ zt,
        const float* __restrict__ xz, float* __restrict__ out,
        int N, int ntile, int out_off)
{
    __shared__ float s[16][65];
    const int tid = threadIdx.x;
    const int b   = blockIdx.x / ntile;
    const int n0  = (blockIdx.x % ntile) * 64;

    for (int i = blockIdx.x * 256 + tid; i < out_off; i += gridDim.x * 256)
        out[i] = xz[i];

    const float* zb = z + (size_t)b * 16 * N;

    {
        const int c = tid >> 4;
        const int n = 4 * (tid & 15);
        if (n0 + n + 3 < N) {
            float4 v = __ldg((const float4*)(zb + (size_t)c * N + n0 + n));
            s[c][n + 0] = v.x; s[c][n + 1] = v.y;
            s[c][n + 2] = v.z; s[c][n + 3] = v.w;
        } else {
            for (int j = 0; j < 4; ++j)
                if (n0 + n + j < N) s[c][n + j] = zb[(size_t)c * N + n0 + n + j];
        }
    }
    __syncthreads();
    {
        const int n = tid >> 2;
        const int g = tid & 3;
        if (n0 + n < N) {
            float4 v = make_float4(s[4*g+0][n], s[4*g+1][n],
                                   s[4*g+2][n], s[4*g+3][n]);
            *(float4*)(zt + ((size_t)b * N + n0 + n) * 16 + 4 * g) = v;
        }
    }

#if __CUDA_ARCH__ >= 900
    cudaTriggerProgrammaticLaunchCompletion();
#endif
}

// ---- Phase 2: 2 targets/warp, 16 lanes/target, 5 batched loads (MLP=5).
__global__ void __launch_bounds__(256) setconv_q2_zt16(
        const float* __restrict__ xz,
        const float* __restrict__ x,
        const float* __restrict__ zt,
        const float* __restrict__ log_scale,
        float* __restrict__ out,
        int BM, int M, int mshift, int N, int out_off)
{
    const int warp = (blockIdx.x * blockDim.x + threadIdx.x) >> 5;
    const int lane = threadIdx.x & 31;
    const int t0   = warp * 2;
    if (t0 >= BM) {
#if __CUDA_ARCH__ >= 900
        cudaGridDependencySynchronize();
#endif
        return;
    }

    const int tgt = lane >> 4;        // target within warp (0/1)
    const int sub = lane & 15;        // r-slot*4 + ch-group
    const int r   = sub >> 2;         // row slot: rows r, r+4, ..., r+16
    const int cg  = sub & 3;          // channel group (float4)

    const bool valid = (t0 + tgt) < BM;
    const int  t     = valid ? (t0 + tgt) : (BM - 1);

    // ---- prologue: independent of zt (overlaps transpose tail under PDL) ----
    const float ls       = __ldg(log_scale);
    const float xz0      = __ldg(xz);
    const float step     = __ldg(xz + 1) - xz0;
    const float alpha    = 0.5f * __expf(-2.0f * ls);   // 1/(2*scale^2)
    const float inv_step = __fdividef(1.0f, step);
    const float dstep    = 4.0f * step;

    const float xv = __ldg(x + t);
    const int   b  = (mshift >= 0) ? (t >> mshift) : (t / M);

    int i0 = (((int)floorf((xv - xz0) * inv_step)) - 8) & ~3;
    i0 = min(max(i0, 0), N - WIN);

    // 32-bit offset into zt (fits: B*N*16 <= 2^22 elements)
    const unsigned off = (unsigned)(b * N + i0) * 16u + (unsigned)sub * 4u;
    const float4*  p   = (const float4*)(zt + off);

    const float d0 = xv - (xz0 + (float)(i0 + r) * step);

#if __CUDA_ARCH__ >= 900
    cudaGridDependencySynchronize();   // zt ready past this point
#endif

    float4 v0, v1, v2, v3, v4;
    asm volatile(
        "ld.global.nc.v4.f32 {%0,%1,%2,%3},     [%20];\n\t"
        "ld.global.nc.v4.f32 {%4,%5,%6,%7},     [%21];\n\t"
        "ld.global.nc.v4.f32 {%8,%9,%10,%11},   [%22];\n\t"
        "ld.global.nc.v4.f32 {%12,%13,%14,%15}, [%23];\n\t"
        "ld.global.nc.v4.f32 {%16,%17,%18,%19}, [%24];\n\t"
        : "=f"(v0.x), "=f"(v0.y), "=f"(v0.z), "=f"(v0.w),
          "=f"(v1.x), "=f"(v1.y), "=f"(v1.z), "=f"(v1.w),
          "=f"(v2.x), "=f"(v2.y), "=f"(v2.z), "=f"(v2.w),
          "=f"(v3.x), "=f"(v3.y), "=f"(v3.z), "=f"(v3.w),
          "=f"(v4.x), "=f"(v4.y), "=f"(v4.z), "=f"(v4.w)
        : "l"(p), "l"(p + 16), "l"(p + 32), "l"(p + 48), "l"(p + 64));

    float4 acc = make_float4(0.f, 0.f, 0.f, 0.f);
#define STEP(K, V)                                                  \
    {   float d = d0 - (float)(K) * dstep;                          \
        float w = __expf(-alpha * d * d);                           \
        acc.x += w * (V).x; acc.y += w * (V).y;                     \
        acc.z += w * (V).z; acc.w += w * (V).w; }
    STEP(0, v0) STEP(1, v1) STEP(2, v2) STEP(3, v3) STEP(4, v4)
#undef STEP

#pragma unroll
    for (int off2 = 4; off2 <= 8; off2 <<= 1) {
        acc.x += __shfl_xor_sync(0xffffffffu, acc.x, off2);
        acc.y += __shfl_xor_sync(0xffffffffu, acc.y, off2);
        acc.z += __shfl_xor_sync(0xffffffffu, acc.z, off2);
        acc.w += __shfl_xor_sync(0xffffffffu, acc.w, off2);
    }

    if (sub < 4 && valid) {
        float4* op = (float4*)(out + out_off + (size_t)t * 16);
        op[cg] = acc;                  // 64B per target, 128B per warp
    }
}

// Generic fallback (full accuracy, 32-pt window).
__global__ void setconv_generic_kernel(const float* __restrict__ xz,
                                       const float* __restrict__ x,
                                       const float* __restrict__ z,
                                       const float* __restrict__ log_scale,
                                       float* __restrict__ out,
                                       int BM, int M, int C, int N, int out_off)
{
    const int tid = blockIdx.x * blockDim.x + threadIdx.x;
    if (tid < out_off) out[tid] = xz[tid];
    if (tid >= BM) return;

    const int b = tid / M;
    const float ls       = *log_scale;
    const float alpha    = 0.5f * __expf(-2.0f * ls);
    const float xz0      = xz[0];
    const float step     = xz[1] - xz[0];
    const float inv_step = 1.0f / step;
    const float xv = x[tid];

    int i0 = (int)floorf((xv - xz0) * inv_step) - 15;
    i0 = min(max(i0, 0), N - 32);

    const float* zb = z + (size_t)b * C * N;

    float w[32];
#pragma unroll
    for (int k = 0; k < 32; ++k) {
        float d = xv - (xz0 + (float)(i0 + k) * step);
        w[k] = __expf(-alpha * d * d);
    }

    for (int cc = 0; cc < C; ++cc) {
        const float* zp = zb + (size_t)cc * N + i0;
        float sacc = 0.0f;
#pragma unroll
        for (int k = 0; k < 32; ++k) sacc += w[k] * zp[k];
        out[out_off + (size_t)tid * C + cc] = sacc;
    }
}

extern "C" void kernel_launch(void* const* d_in, const int* in_sizes, int n_in,
                              void* d_out, int out_size)
{
    const float* xz = (const float*)d_in[0];   // [N,1]
    const float* x  = (const float*)d_in[1];   // [B,M,1]
    const float* z  = (const float*)d_in[2];   // [B,C,N]
    const float* ls = (const float*)d_in[3];   // scalar

    const int N   = in_sizes[0];
    const int BM  = in_sizes[1];
    const int BCN = in_sizes[2];
    const int BC  = BCN / N;

    int C, out_off;
    if ((out_size - N) > 0 && (out_size - N) % BM == 0 &&
        (BC % ((out_size - N) / BM)) == 0) {
        C = (out_size - N) / BM;   // tuple output: [xz | out]
        out_off = N;
    } else {
        C = out_size / BM;
        out_off = 0;
    }
    const int B = BC / C;
    const int M = BM / B;

    float* out = (float*)d_out;

    if (C == 16 && N >= 32 && (size_t)BCN <= (size_t)(1 << 22)) {
        float* zt;
        cudaGetSymbolAddress((void**)&zt, g_zt);

        int mshift = -1;
        if ((M & (M - 1)) == 0) { mshift = 0; while ((1 << mshift) < M) ++mshift; }

        const int ntile = (N + 63) / 64;
        transpose_z16<<<B * ntile, 256>>>(z, zt, xz, out, N, ntile, out_off);

        const long long warps = (BM + 1) / 2;
        const int threads = 256;
        const int blocks  = (int)((warps * 32 + threads - 1) / threads);

        // PDL launch: compute prologue overlaps transpose tail.
        cudaLaunchConfig_t cfg = {};
        cfg.gridDim  = dim3((unsigned)blocks, 1, 1);
        cfg.blockDim = dim3((unsigned)threads, 1, 1);
        cfg.dynamicSmemBytes = 0;
        cfg.stream = 0;
        cudaLaunchAttribute attrs[1];
        attrs[0].id = cudaLaunchAttributeProgrammaticStreamSerialization;
        attrs[0].val.programmaticStreamSerializationAllowed = 1;
        cfg.attrs = attrs;
        cfg.numAttrs = 1;

        cudaError_t e = cudaLaunchKernelEx(&cfg, setconv_q2_zt16,
                                           xz, x, zt, ls, out,
                                           BM, M, mshift, N, out_off);
        if (e != cudaSuccess) {
            // fallback: plain serialized launch (R9 behavior)
            setconv_q2_zt16<<<blocks, threads>>>(xz, x, zt, ls, out,
                                                 BM, M, mshift, N, out_off);
        }
    } else {
        const int threads = 128;
        const int work    = (BM > out_off) ? BM : out_off;
        const int blocks  = (work + threads - 1) / threads;
        setconv_generic_kernel<<<blocks, threads>>>(xz, x, z, ls, out, BM, M, C, N, out_off);
    }
}